// round 1
// baseline (speedup 1.0000x reference)
#include <cuda_runtime.h>

#define CDIM 128
#define KTOT 1024
#define MV   128     // vectors per block
#define NT   128     // codes per tile
#define HW   4096    // H*W
#define ZP   132     // zsT pitch (multiple of 4 for float4, 132%32==4 avoids conflicts)

// scratch (no allocations allowed)
__device__ float  g_enorm[KTOT];
__device__ int    g_used[KTOT];
__device__ double g_sq;

// smem: zsT[CDIM][ZP] + cs[NT][CDIM] + zn[MV] + se[NT]
#define SMEM_FLOATS (CDIM*ZP + NT*CDIM + MV + NT)
#define SMEM_BYTES  (SMEM_FLOATS * 4)

// ---------------------------------------------------------------------------
// Kernel 1: init — zero usage flags / MSE accumulator, precompute ||e_k||^2
// ---------------------------------------------------------------------------
__global__ void vq_init(const float* __restrict__ cb) {
    int k = threadIdx.x;               // blockDim = 1024 = KTOT
    g_used[k] = 0;
    if (k == 0) g_sq = 0.0;
    const float* row = cb + k * CDIM;
    float s = 0.f;
    #pragma unroll 8
    for (int c = 0; c < CDIM; ++c) s = __fmaf_rn(row[c], row[c], s);
    g_enorm[k] = s;
}

// ---------------------------------------------------------------------------
// Kernel 2: main — distance GEMM + argmin + gather epilogue + MSE partial
// ---------------------------------------------------------------------------
__global__ void __launch_bounds__(256, 1) vq_main(
    const float* __restrict__ z, const float* __restrict__ cb,
    float* __restrict__ out)
{
    extern __shared__ float sm[];
    float* zsT = sm;                    // [CDIM][ZP]   z tile, transposed
    float* cs  = sm + CDIM * ZP;        // [NT][CDIM]   codebook tile (row-major)
    float* zn  = cs + NT * CDIM;        // [MV]         ||z||^2 per vector
    float* se  = zn + MV;               // [NT]         ||e||^2 per tile code
    // overlays used after the K loop (cs region is free then):
    float* rbest = cs;                  // [MV][17]
    int*   rki   = (int*)(cs + MV * 17);// [MV][17]

    const int tid = threadIdx.x;
    const int n0  = blockIdx.x * MV;
    const int b   = n0 >> 12;           // n0 / HW
    const int p0  = n0 & (HW - 1);
    const float* zbase = z + (size_t)b * CDIM * HW + p0;

    // ---- stage z: (coalesced float4 reads, conflict-free STS) ----
    #pragma unroll
    for (int it = 0; it < 16; ++it) {
        int idx = it * 256 + tid;                 // 0..4095 float4 slots
        int c   = idx >> 5;
        int v4  = (idx & 31) << 2;
        float4 val = *reinterpret_cast<const float4*>(zbase + (size_t)c * HW + v4);
        float* dst = zsT + c * ZP + v4;
        dst[0] = val.x; dst[1] = val.y; dst[2] = val.z; dst[3] = val.w;
    }
    __syncthreads();

    // ---- ||z||^2 per vector (sequential ascending c, IEEE fma) ----
    if (tid < MV) {
        float s = 0.f;
        #pragma unroll 8
        for (int c = 0; c < CDIM; ++c) {
            float x = zsT[c * ZP + tid];
            s = __fmaf_rn(x, x, s);
        }
        zn[tid] = s;
    }
    __syncthreads();

    const int v4 = (tid & 15) << 2;     // vector group base (covers v4..v4+3, v4+64..v4+67)
    const int k4 = (tid >> 4) << 2;     // code group base   (covers k4..k4+3, k4+64..k4+67)

    float vnr[8];
    #pragma unroll
    for (int i = 0; i < 8; ++i) vnr[i] = zn[v4 + (i < 4 ? i : 60 + i)];

    float best[8]; int bestk[8];
    #pragma unroll
    for (int i = 0; i < 8; ++i) { best[i] = 3.4e38f; bestk[i] = 0; }

    for (int kt = 0; kt < KTOT / NT; ++kt) {
        // ---- stage codebook tile (fully coalesced, conflict-free) ----
        const float* cbt = cb + (size_t)kt * NT * CDIM;
        #pragma unroll
        for (int it = 0; it < 16; ++it) {
            int idx = it * 256 + tid;
            int k   = idx >> 5;
            int c4  = (idx & 31) << 2;
            float4 val = *reinterpret_cast<const float4*>(cbt + k * CDIM + c4);
            *reinterpret_cast<float4*>(cs + k * CDIM + c4) = val;
        }
        if (tid < NT) se[tid] = g_enorm[kt * NT + tid];
        __syncthreads();

        // ---- 8x8 register micro-tile GEMM over C ----
        float acc[8][8];
        #pragma unroll
        for (int i = 0; i < 8; ++i)
            #pragma unroll
            for (int j = 0; j < 8; ++j) acc[i][j] = 0.f;

        #pragma unroll 4
        for (int c = 0; c < CDIM; ++c) {
            float4 za = *reinterpret_cast<const float4*>(zsT + c * ZP + v4);
            float4 zc = *reinterpret_cast<const float4*>(zsT + c * ZP + v4 + 64);
            float av[8] = {za.x, za.y, za.z, za.w, zc.x, zc.y, zc.z, zc.w};
            float bv[8];
            #pragma unroll
            for (int j = 0; j < 4; ++j) bv[j]     = cs[(k4 + j) * CDIM + c];
            #pragma unroll
            for (int j = 0; j < 4; ++j) bv[4 + j] = cs[(k4 + 64 + j) * CDIM + c];
            #pragma unroll
            for (int i = 0; i < 8; ++i)
                #pragma unroll
                for (int j = 0; j < 8; ++j)
                    acc[i][j] = __fmaf_rn(av[i], bv[j], acc[i][j]);
        }

        // ---- scores + running argmin (reference formula & rounding) ----
        #pragma unroll
        for (int j = 0; j < 8; ++j) {
            int kl = (j < 4) ? (k4 + j) : (k4 + 60 + j);   // ascending within thread
            float ek = se[kl];
            int   kg = kt * NT + kl;
            #pragma unroll
            for (int i = 0; i < 8; ++i) {
                // d = fl( fl(znorm + enorm) - fl(2 * dot) )  — matches jnp expression
                float d = __fsub_rn(__fadd_rn(vnr[i], ek), __fmul_rn(2.0f, acc[i][j]));
                if (d < best[i]) { best[i] = d; bestk[i] = kg; }  // strict <: first idx wins
            }
        }
        __syncthreads();   // before overwriting cs/se next tile
    }

    // ---- cross-thread argmin reduction (lexicographic: score, then index) ----
    int g = tid >> 4;
    #pragma unroll
    for (int i = 0; i < 8; ++i) {
        int v = v4 + (i < 4 ? i : 60 + i);
        rbest[v * 17 + g] = best[i];
        rki  [v * 17 + g] = bestk[i];
    }
    __syncthreads();

    float errsum = 0.f;
    if (tid < MV) {
        int v = tid;
        float bb = rbest[v * 17]; int bk = rki[v * 17];
        #pragma unroll
        for (int gg = 1; gg < 16; ++gg) {
            float nb = rbest[v * 17 + gg];
            int   nk = rki  [v * 17 + gg];
            if (nb < bb || (nb == bb && nk < bk)) { bb = nb; bk = nk; }
        }
        g_used[bk] = 1;

        // epilogue: z_q_st = fl(z + fl(z_q - z)) written in (B,C,H,W); MSE partial
        const float4* crow = reinterpret_cast<const float4*>(cb + (size_t)bk * CDIM);
        float* ob = out + (size_t)b * CDIM * HW + p0 + v;
        #pragma unroll 8
        for (int c4 = 0; c4 < 32; ++c4) {
            float4 e4 = crow[c4];
            float ee[4] = {e4.x, e4.y, e4.z, e4.w};
            #pragma unroll
            for (int jj = 0; jj < 4; ++jj) {
                int c = c4 * 4 + jj;
                float zv = zsT[c * ZP + v];
                float t  = __fsub_rn(ee[jj], zv);          // z_q - z
                ob[(size_t)c * HW] = __fadd_rn(zv, t);     // straight-through value
                errsum = __fmaf_rn(t, t, errsum);
            }
        }
    }

    // ---- block reduction of squared error -> double atomic ----
    float* sred = zn;   // zn no longer needed
    __syncthreads();
    if (tid < MV) sred[tid] = errsum;
    __syncthreads();
    if (tid < 64) sred[tid] = __fadd_rn(sred[tid], sred[tid + 64]);
    __syncthreads();
    if (tid < 32) {
        float s = __fadd_rn(sred[tid], sred[tid + 32]);
        #pragma unroll
        for (int off = 16; off; off >>= 1)
            s = __fadd_rn(s, __shfl_down_sync(0xffffffffu, s, off));
        if (tid == 0) atomicAdd(&g_sq, (double)s);
    }
}

// ---------------------------------------------------------------------------
// Kernel 3: finalize — vq_loss + usage scalars
// ---------------------------------------------------------------------------
__global__ void vq_fin(float* __restrict__ out, int npix) {
    __shared__ int cnt[32];
    int tid = threadIdx.x;             // 1024 threads
    int u = g_used[tid] ? 1 : 0;
    #pragma unroll
    for (int off = 16; off; off >>= 1) u += __shfl_down_sync(0xffffffffu, u, off);
    if ((tid & 31) == 0) cnt[tid >> 5] = u;
    __syncthreads();
    if (tid == 0) {
        int total = 0;
        #pragma unroll
        for (int i = 0; i < 32; ++i) total += cnt[i];
        float m  = (float)(g_sq / (double)npix);
        // vq_loss = codebook_loss + 0.25 * commitment_loss (identical forward values)
        float vq = __fadd_rn(m, __fmul_rn(0.25f, m));
        out[npix]     = vq;
        out[npix + 1] = (float)total * (1.0f / 1024.0f);  // exact /1024
    }
}

// ---------------------------------------------------------------------------
extern "C" void kernel_launch(void* const* d_in, const int* in_sizes, int n_in,
                              void* d_out, int out_size) {
    const float* z  = (const float*)d_in[0];
    const float* cb = (const float*)d_in[1];
    float* out = (float*)d_out;
    int npix = out_size - 2;                    // 8388608
    int nvec = npix / CDIM;                     // 65536
    int blocks = nvec / MV;                     // 512

    cudaFuncSetAttribute(vq_main, cudaFuncAttributeMaxDynamicSharedMemorySize, SMEM_BYTES);

    vq_init<<<1, KTOT>>>(cb);
    vq_main<<<blocks, 256, SMEM_BYTES>>>(z, cb, out);
    vq_fin<<<1, KTOT>>>(out, npix);
}